// round 4
// baseline (speedup 1.0000x reference)
#include <cuda_runtime.h>
#include <cstdint>

#define Hh   64
#define Ww   176
#define HW   (Hh * Ww)
#define NCAM 2
#define NPIX (NCAM * HW)
#define Cc   128
#define Dd   80
#define Oo   208
#define TPV0 200
#define TPV1 704
#define TPV2 32
#define XY_CELLS (TPV0 * TPV1)
#define XZ_CELLS (TPV1 * TPV2)
#define YZ_CELLS (TPV0 * TPV2)

#define PC_MIN_X (-54.0f)
#define PC_MIN_Y (-54.0f)
#define PC_MIN_Z (-5.0f)
#define PROB_TH 1e-4f

__device__ float4 g_xy[XY_CELLS * 32];
__device__ float4 g_xz[XZ_CELLS * 32];
__device__ float4 g_yz[YZ_CELLS * 32];
__device__ float4 g_featv[NPIX * 32];
__device__ float4 g_probv[NPIX * 20];

// ---- phase 1: per-pixel 208x128 GEMV + softmax(80) ----
__global__ __launch_bounds__(128, 1)
void prep_kernel(const float* __restrict__ img,
                 const float* __restrict__ Wm,
                 const float* __restrict__ bias) {
    extern __shared__ float sm[];
    float* sW = sm;
    float* sf = sm + Oo * Cc;
    const int tid = threadIdx.x;

    const float4* W4 = (const float4*)Wm;
    float4* sW4 = (float4*)sW;
    for (int i = tid; i < (Oo * Cc) / 4; i += 128) sW4[i] = W4[i];

    const int p  = blockIdx.x * 128 + tid;
    const int n  = p / HW;
    const int hw = p % HW;
    const float* src = img + (size_t)n * Cc * HW + hw;
#pragma unroll 4
    for (int c = 0; c < Cc; ++c) sf[c * 128 + tid] = src[(size_t)c * HW];
    __syncthreads();

    float lg[Dd];
    float m = -1e30f;
#pragma unroll 1
    for (int o = 0; o < Dd; o += 4) {
        float a0 = __ldg(&bias[o]), a1 = __ldg(&bias[o + 1]);
        float a2 = __ldg(&bias[o + 2]), a3 = __ldg(&bias[o + 3]);
        const float* w0 = sW + o * Cc;
#pragma unroll 8
        for (int c = 0; c < Cc; ++c) {
            float f = sf[c * 128 + tid];
            a0 += w0[c] * f;
            a1 += w0[Cc + c] * f;
            a2 += w0[2 * Cc + c] * f;
            a3 += w0[3 * Cc + c] * f;
        }
        lg[o] = a0; lg[o + 1] = a1; lg[o + 2] = a2; lg[o + 3] = a3;
        m = fmaxf(m, fmaxf(fmaxf(a0, a1), fmaxf(a2, a3)));
    }
    float s = 0.f;
#pragma unroll 1
    for (int o = 0; o < Dd; ++o) { float e = expf(lg[o] - m); lg[o] = e; s += e; }
    const float inv = 1.0f / s;
    float4* probe = g_probv + (size_t)p * 20;
#pragma unroll 1
    for (int o = 0; o < Dd; o += 4) {
        float4 v;
        v.x = lg[o] * inv;     v.y = lg[o + 1] * inv;
        v.z = lg[o + 2] * inv; v.w = lg[o + 3] * inv;
        v.x = (v.x > PROB_TH) ? v.x : 0.f;
        v.y = (v.y > PROB_TH) ? v.y : 0.f;
        v.z = (v.z > PROB_TH) ? v.z : 0.f;
        v.w = (v.w > PROB_TH) ? v.w : 0.f;
        probe[o >> 2] = v;
    }

    float4* fout = g_featv + (size_t)p * 32;
#pragma unroll 1
    for (int o = Dd; o < Oo; o += 4) {
        float a0 = __ldg(&bias[o]), a1 = __ldg(&bias[o + 1]);
        float a2 = __ldg(&bias[o + 2]), a3 = __ldg(&bias[o + 3]);
        const float* w0 = sW + o * Cc;
#pragma unroll 8
        for (int c = 0; c < Cc; ++c) {
            float f = sf[c * 128 + tid];
            a0 += w0[c] * f;
            a1 += w0[Cc + c] * f;
            a2 += w0[2 * Cc + c] * f;
            a3 += w0[3 * Cc + c] * f;
        }
        fout[(o - Dd) >> 2] = make_float4(a0, a1, a2, a3);
    }
}

// ---- phase 2: IEEE-exact geometry; voxelize via reciprocal-multiply
//      (matches XLA's jit-time  x/const -> x * fl(1/const)  rewrite) ----
__global__ __launch_bounds__(96, 8)
void scatter_kernel(const float* __restrict__ intr,
                    const float* __restrict__ extr) {
    __shared__ float4 sfeat[32];
    __shared__ float  spw[Dd];
    __shared__ int    sidx[3][Dd];

    const int p   = blockIdx.x;
    const int tid = threadIdx.x;

    if (tid < 32) sfeat[tid] = g_featv[(size_t)p * 32 + tid];

    if (tid < Dd) {
        spw[tid] = ((const float*)g_probv)[(size_t)p * Dd + tid];

        const int n  = p / HW;
        const int hw = p % HW;
        const int h  = hw / Ww;
        const int u  = hw % Ww;

        // K upper-triangular -> inverse via back-substitution (round-to-nearest,
        // fast-math-immune; preserves the exact-zero degenerate rays).
        const float* Kp = intr + n * 9;
        const float K00 = Kp[0], K02 = Kp[2];
        const float K11 = Kp[4], K12 = Kp[5];
        const float K22 = Kp[8];
        const float x22 = __fdiv_rn(1.0f, K22);
        const float k00 = __fdiv_rn(1.0f, K00);
        const float k11 = __fdiv_rn(1.0f, K11);
        const float k12 = __fdiv_rn(__fmul_rn(-K12, x22), K11);
        const float k02 = __fdiv_rn(__fmul_rn(-K02, x22), K00);

        const float uf = (float)u, vf = (float)h;
        const float rx = __fadd_rn(__fmul_rn(k00, uf), k02);
        const float ry = __fadd_rn(__fmul_rn(k11, vf), k12);
        const float rz = x22;

        const float step = 48.0f / 79.0f;
        const float dsv = __fadd_rn(__fmul_rn(step, (float)tid), 2.0f);

        const float cx = __fmul_rn(rx, dsv);
        const float cy = __fmul_rn(ry, dsv);
        const float cz = __fmul_rn(rz, dsv);

        const float* E = extr + n * 16;
        const float wx = __fadd_rn(__fadd_rn(__fadd_rn(__fmul_rn(E[0], cx),
                         __fmul_rn(E[1], cy)), __fmul_rn(E[2],  cz)), E[3]);
        const float wy = __fadd_rn(__fadd_rn(__fadd_rn(__fmul_rn(E[4], cx),
                         __fmul_rn(E[5], cy)), __fmul_rn(E[6],  cz)), E[7]);
        const float wz = __fadd_rn(__fadd_rn(__fadd_rn(__fmul_rn(E[8], cx),
                         __fmul_rn(E[9], cy)), __fmul_rn(E[10], cz)), E[11]);

        // Reciprocal-multiply voxelization. Constants are the float32
        // round-to-nearest of 1/vs (computed at compile time in f32).
        const float RCP_XY = 1.0f / 0.54f;   // fl(1/0.54f) = 1.8518518
        const float RCP_Z  = 4.0f;           // 1/0.25 exact
        int vx = (int)__fmul_rn(__fsub_rn(wx, PC_MIN_X), RCP_XY);
        int vy = (int)__fmul_rn(__fsub_rn(wy, PC_MIN_Y), RCP_XY);
        int vz = (int)__fmul_rn(__fsub_rn(wz, PC_MIN_Z), RCP_Z);
        vx = min(max(vx, 0), TPV1 - 1);
        vy = min(max(vy, 0), TPV0 - 1);
        vz = min(max(vz, 0), TPV2 - 1);

        sidx[0][tid] = vy * TPV1 + vx;
        sidx[1][tid] = vx * TPV2 + vz;
        sidx[2][tid] = vy * TPV2 + vz;
    }
    __syncthreads();

    const int wid  = tid >> 5;
    const int lane = tid & 31;
    const float4 fv = sfeat[lane];
    float* base = (wid == 0) ? (float*)g_xy : (wid == 1) ? (float*)g_xz : (float*)g_yz;
    const int* idx = sidx[wid];

    int   cur = idx[0];
    float acc = spw[0];
#pragma unroll 1
    for (int d = 1; d < Dd; ++d) {
        const int   ix = idx[d];
        const float w  = spw[d];
        if (ix == cur) {
            acc += w;
        } else {
            if (acc > 0.f) {
                float* dst = base + ((size_t)cur << 7) + (lane << 2);
                asm volatile("red.global.add.v4.f32 [%0], {%1,%2,%3,%4};"
                             :: "l"(dst),
                                "f"(fv.x * acc), "f"(fv.y * acc),
                                "f"(fv.z * acc), "f"(fv.w * acc)
                             : "memory");
            }
            cur = ix;
            acc = w;
        }
    }
    if (acc > 0.f) {
        float* dst = base + ((size_t)cur << 7) + (lane << 2);
        asm volatile("red.global.add.v4.f32 [%0], {%1,%2,%3,%4};"
                     :: "l"(dst),
                        "f"(fv.x * acc), "f"(fv.y * acc),
                        "f"(fv.z * acc), "f"(fv.w * acc)
                     : "memory");
    }
}

// ---- phase 3: transpose [cell][C] -> [C][cell] ----
__global__ __launch_bounds__(256)
void transpose_kernel(const float* __restrict__ src, float* __restrict__ dst, int cells) {
    __shared__ float t[32][33];
    const int cell0 = blockIdx.x * 32;
    const int c0    = blockIdx.y * 32;
    const int tx = threadIdx.x, ty = threadIdx.y;
#pragma unroll
    for (int i = ty; i < 32; i += 8)
        t[i][tx] = src[(size_t)(cell0 + i) * Cc + c0 + tx];
    __syncthreads();
#pragma unroll
    for (int i = ty; i < 32; i += 8)
        dst[(size_t)(c0 + i) * cells + cell0 + tx] = t[tx][i];
}

extern "C" void kernel_launch(void* const* d_in, const int* in_sizes, int n_in,
                              void* d_out, int out_size) {
    const float* img  = (const float*)d_in[0];
    const float* intr = (const float*)d_in[2];
    const float* extr = (const float*)d_in[3];
    const float* Wm   = (const float*)d_in[4];
    const float* bias = (const float*)d_in[5];
    float* out = (float*)d_out;

    void *pxy, *pxz, *pyz;
    cudaGetSymbolAddress(&pxy, g_xy);
    cudaGetSymbolAddress(&pxz, g_xz);
    cudaGetSymbolAddress(&pyz, g_yz);
    cudaMemsetAsync(pxy, 0, sizeof(g_xy));
    cudaMemsetAsync(pxz, 0, sizeof(g_xz));
    cudaMemsetAsync(pyz, 0, sizeof(g_yz));

    const int smem = (Oo * Cc + 128 * 128) * (int)sizeof(float);
    cudaFuncSetAttribute(prep_kernel, cudaFuncAttributeMaxDynamicSharedMemorySize, smem);
    prep_kernel<<<NPIX / 128, 128, smem>>>(img, Wm, bias);

    scatter_kernel<<<NPIX, 96>>>(intr, extr);

    dim3 tb(32, 8);
    transpose_kernel<<<dim3(XY_CELLS / 32, Cc / 32), tb>>>((const float*)pxy, out, XY_CELLS);
    transpose_kernel<<<dim3(XZ_CELLS / 32, Cc / 32), tb>>>((const float*)pxz,
                         out + (size_t)Cc * XY_CELLS, XZ_CELLS);
    transpose_kernel<<<dim3(YZ_CELLS / 32, Cc / 32), tb>>>((const float*)pyz,
                         out + (size_t)Cc * (XY_CELLS + XZ_CELLS), YZ_CELLS);
}